// round 9
// baseline (speedup 1.0000x reference)
#include <cuda_runtime.h>

#define NJ   24
#define TPB  128          // threads per block
#define TILE 512          // samples per block: 4 per thread (2 f32x2 streams)
#define ROWF 32           // staged floats per row (8 chunks of 4: 24 valid + 8 pad)

typedef unsigned long long u64;

__device__ __forceinline__ u64 pack2(float lo, float hi) {
    u64 r;
    asm("mov.b64 %0, {%1, %2};" : "=l"(r) : "f"(lo), "f"(hi));
    return r;
}
__device__ __forceinline__ void unpack2(u64 v, float& lo, float& hi) {
    asm("mov.b64 {%0, %1}, %2;" : "=f"(lo), "=f"(hi) : "l"(v));
}
// packed dual-sample FMA on both 32-bit halves (Blackwell FFMA2 path)
__device__ __forceinline__ u64 ffma2(u64 a, u64 b, u64 c) {
    u64 d;
    asm("fma.rn.f32x2 %0, %1, %2, %3;" : "=l"(d) : "l"(a), "l"(b), "l"(c));
    return d;
}

__global__ __launch_bounds__(TPB, 2)
void se1d_kernel(const float* __restrict__ x,
                 const float* __restrict__ W1,
                 const float* __restrict__ b1,
                 const float* __restrict__ W2,
                 const float* __restrict__ b2,
                 float* __restrict__ out,
                 int B)
{
    // skeleton parents; topo order is identity (parent[i] < i for all i)
    constexpr int PAR[NJ] = {-1,0,0,0,1,2,3,4,5,6,7,8,9,9,9,12,13,14,16,17,18,19,20,21};

    extern __shared__ char smem[];
    float* stage = reinterpret_cast<float*>(smem);              // TILE*ROWF*4 = 64 KB
    u64* sW1 = reinterpret_cast<u64*>(smem + TILE * ROWF * 4);  // 24*7*8 u64: [w0..w6, b1]
    u64* sW2 = sW1 + NJ * 7 * 8;                                // 24*6*8 u64: [w0..w6, b2]
    // smem total = 65536 + 19968 = 85504 B -> 2 blocks/SM

    const int t    = threadIdx.x;
    const int tile = blockIdx.x * TILE;

    // ---- cooperative weight load: pad each row to 8 u64 {w,w} with bias in slot 7 ----
    for (int i = t; i < NJ * 56; i += TPB) {
        int j = i / 56, rem = i % 56, r = rem >> 3, c = rem & 7;
        float v = (c < 7) ? W1[j * 49 + r * 7 + c] : b1[j * 7 + r];
        sW1[i] = pack2(v, v);
    }
    for (int i = t; i < NJ * 48; i += TPB) {
        int j = i / 48, rem = i % 48, r = rem >> 3, c = rem & 7;
        float v = (c < 7) ? W2[j * 42 + r * 7 + c] : b2[j * 6 + r];
        sW2[i] = pack2(v, v);
    }

    // ---- 4 sample rows per thread: stream0 = (t, t+128), stream1 = (t+256, t+384) ----
    const int r0 = tile + t, r1 = tile + t + TPB;
    const int r2 = tile + t + 2 * TPB, r3 = tile + t + 3 * TPB;
    const bool v0 = r0 < B, v1 = r1 < B, v2 = r2 < B, v3 = r3 < B;
    const float4* px0 = reinterpret_cast<const float4*>(x + (size_t)r0 * NJ);
    const float4* px1 = reinterpret_cast<const float4*>(x + (size_t)r1 * NJ);
    const float4* px2 = reinterpret_cast<const float4*>(x + (size_t)r2 * NJ);
    const float4* px3 = reinterpret_cast<const float4*>(x + (size_t)r3 * NJ);
    const float4 fz = make_float4(0.f, 0.f, 0.f, 0.f);
    float4 c0 = v0 ? px0[0] : fz;
    float4 c1 = v1 ? px1[0] : fz;
    float4 c2 = v2 ? px2[0] : fz;
    float4 c3 = v3 ? px3[0] : fz;
    float4 n0 = fz, n1 = fz, n2 = fz, n3 = fz;

    __syncthreads();   // weights ready

    float4* out4 = reinterpret_cast<float4*>(out);
    u64 feat0[NJ][6], feat1[NJ][6];   // liveness-pruned after full unroll
    const int sw = t & 7;

    #pragma unroll
    for (int j = 0; j < NJ; j++) {
        if ((j & 3) == 0) {
            const int q = (j >> 2) + 1;
            if (q < 6) {
                n0 = v0 ? px0[q] : fz; n1 = v1 ? px1[q] : fz;
                n2 = v2 ? px2[q] : fz; n3 = v3 ? px3[q] : fz;
            }
        }
        const int cc = j & 3;
        float xa = (cc==0)?c0.x:(cc==1)?c0.y:(cc==2)?c0.z:c0.w;
        float xb = (cc==0)?c1.x:(cc==1)?c1.y:(cc==2)?c1.z:c1.w;
        float xc = (cc==0)?c2.x:(cc==1)?c2.y:(cc==2)?c2.z:c2.w;
        float xd = (cc==0)?c3.x:(cc==1)?c3.y:(cc==2)?c3.z:c3.w;
        const u64 xp0 = pack2(xa, xb);
        const u64 xp1 = pack2(xc, xd);

        const int p = PAR[j];
        const u64* w1j = sW1 + j * 56;

        // h = relu([x_j, parent_feat] @ W1^T + b1): each weight quad serves BOTH streams
        u64 h0[7], h1[7];
        #pragma unroll
        for (int r = 0; r < 7; r++) {
            const ulonglong2* q4 = reinterpret_cast<const ulonglong2*>(w1j + r * 8);
            ulonglong2 q0 = q4[0], q1 = q4[1], q2 = q4[2], q3 = q4[3];
            u64 a0 = q3.y, a1 = q3.y;            // bias
            a0 = ffma2(xp0, q0.x, a0);
            a1 = ffma2(xp1, q0.x, a1);
            if (p >= 0) {
                a0 = ffma2(feat0[p][0], q0.y, a0);  a1 = ffma2(feat1[p][0], q0.y, a1);
                a0 = ffma2(feat0[p][1], q1.x, a0);  a1 = ffma2(feat1[p][1], q1.x, a1);
                a0 = ffma2(feat0[p][2], q1.y, a0);  a1 = ffma2(feat1[p][2], q1.y, a1);
                a0 = ffma2(feat0[p][3], q2.x, a0);  a1 = ffma2(feat1[p][3], q2.x, a1);
                a0 = ffma2(feat0[p][4], q2.y, a0);  a1 = ffma2(feat1[p][4], q2.y, a1);
                a0 = ffma2(feat0[p][5], q3.x, a0);  a1 = ffma2(feat1[p][5], q3.x, a1);
            }
            float fa, fb; unpack2(a0, fa, fb);
            h0[r] = pack2(fmaxf(fa, 0.f), fmaxf(fb, 0.f));
            unpack2(a1, fa, fb);
            h1[r] = pack2(fmaxf(fa, 0.f), fmaxf(fb, 0.f));
        }

        // o = relu(h @ W2^T + b2)
        const u64* w2j = sW2 + j * 48;
        float oa0[6], ob0[6], oa1[6], ob1[6];    // [row t],[row t+128],[row t+256],[row t+384]
        #pragma unroll
        for (int r = 0; r < 6; r++) {
            const ulonglong2* q4 = reinterpret_cast<const ulonglong2*>(w2j + r * 8);
            ulonglong2 q0 = q4[0], q1 = q4[1], q2 = q4[2], q3 = q4[3];
            u64 a0 = q3.y, a1 = q3.y;            // bias
            a0 = ffma2(h0[0], q0.x, a0);  a1 = ffma2(h1[0], q0.x, a1);
            a0 = ffma2(h0[1], q0.y, a0);  a1 = ffma2(h1[1], q0.y, a1);
            a0 = ffma2(h0[2], q1.x, a0);  a1 = ffma2(h1[2], q1.x, a1);
            a0 = ffma2(h0[3], q1.y, a0);  a1 = ffma2(h1[3], q1.y, a1);
            a0 = ffma2(h0[4], q2.x, a0);  a1 = ffma2(h1[4], q2.x, a1);
            a0 = ffma2(h0[5], q2.y, a0);  a1 = ffma2(h1[5], q2.y, a1);
            a0 = ffma2(h0[6], q3.x, a0);  a1 = ffma2(h1[6], q3.x, a1);
            float fa, fb; unpack2(a0, fa, fb);
            fa = fmaxf(fa, 0.f); fb = fmaxf(fb, 0.f);
            oa0[r] = fa; ob0[r] = fb;
            feat0[j][r] = pack2(fa, fb);
            unpack2(a1, fa, fb);
            fa = fmaxf(fa, 0.f); fb = fmaxf(fb, 0.f);
            oa1[r] = fa; ob1[r] = fb;
            feat1[j][r] = pack2(fa, fb);
        }

        // stage the 6 outputs for all 4 sample rows (XOR-swizzled 16B chunks)
        {
            const int cbs = (j & 3) * 6;         // phase-local channel base (0..18)
            #pragma unroll
            for (int k2 = 0; k2 < 3; k2++) {
                const int e     = cbs + 2 * k2;  // compile-time
                const int chunk = e >> 2;
                const int off   = e & 3;
                const int so    = ((chunk ^ sw) << 2) + off;
                *reinterpret_cast<float2*>(&stage[(t           ) * ROWF + so]) =
                    make_float2(oa0[2*k2], oa0[2*k2+1]);
                *reinterpret_cast<float2*>(&stage[(t +     TPB) * ROWF + so]) =
                    make_float2(ob0[2*k2], ob0[2*k2+1]);
                *reinterpret_cast<float2*>(&stage[(t + 2 * TPB) * ROWF + so]) =
                    make_float2(oa1[2*k2], oa1[2*k2+1]);
                *reinterpret_cast<float2*>(&stage[(t + 3 * TPB) * ROWF + so]) =
                    make_float2(ob1[2*k2], ob1[2*k2+1]);
            }
        }

        // every 4 joints: flush 24 staged channels with coalesced STG.128
        if ((j & 3) == 3) {
            const int ph = j >> 2;
            __syncthreads();
            #pragma unroll
            for (int i = 0; i < 24; i++) {       // TILE*6 float4 / TPB threads
                const int kk = t + i * TPB;
                const int s  = kk / 6;
                const int c4 = kk % 6;
                float4 v = *reinterpret_cast<const float4*>(
                    &stage[s * ROWF + ((c4 ^ (s & 7)) << 2)]);
                const int gr = tile + s;
                if (gr < B)
                    out4[(size_t)gr * 36 + ph * 6 + c4] = v;
            }
            __syncthreads();
            if (j + 1 < NJ) { c0 = n0; c1 = n1; c2 = n2; c3 = n3; }
        }
    }
}

extern "C" void kernel_launch(void* const* d_in, const int* in_sizes, int n_in,
                              void* d_out, int out_size)
{
    const float* x  = (const float*)d_in[0];
    const float* W1 = (const float*)d_in[1];
    const float* b1 = (const float*)d_in[2];
    const float* W2 = (const float*)d_in[3];
    const float* b2 = (const float*)d_in[4];
    float* out = (float*)d_out;

    const int B = in_sizes[0] / NJ;
    const int blocks = (B + TILE - 1) / TILE;
    const size_t shm = (size_t)TILE * ROWF * 4          // staging: 65536 B
                     + (size_t)(NJ * 56 + NJ * 48) * 8; // weights: 19968 B

    cudaFuncSetAttribute(se1d_kernel, cudaFuncAttributeMaxDynamicSharedMemorySize, (int)shm);
    se1d_kernel<<<blocks, TPB, shm>>>(x, W1, b1, W2, b2, out, B);
}

// round 10
// speedup vs baseline: 1.4419x; 1.4419x over previous
#include <cuda_runtime.h>

#define NJ   24
#define TPB  128          // threads per block
#define TILE 256          // samples per block (pair rows t and t+128)
#define ROWF 32           // staged floats per row (8 chunks of 4: 24 valid + 8 pad)

typedef unsigned long long u64;

// duplicated {w,w} weight tables in global memory (L1-resident after first touch)
__device__ u64 gW1[NJ * 56];   // per joint: 7 rows of [w0..w6, b1] as u64 pairs
__device__ u64 gW2[NJ * 48];   // per joint: 6 rows of [w0..w6, b2] as u64 pairs

__device__ __forceinline__ u64 pack2(float lo, float hi) {
    u64 r;
    asm("mov.b64 %0, {%1, %2};" : "=l"(r) : "f"(lo), "f"(hi));
    return r;
}
__device__ __forceinline__ void unpack2(u64 v, float& lo, float& hi) {
    asm("mov.b64 {%0, %1}, %2;" : "=f"(lo), "=f"(hi) : "l"(v));
}
// packed dual-sample FMA on both 32-bit halves (Blackwell FFMA2 path)
__device__ __forceinline__ u64 ffma2(u64 a, u64 b, u64 c) {
    u64 d;
    asm("fma.rn.f32x2 %0, %1, %2, %3;" : "=l"(d) : "l"(a), "l"(b), "l"(c));
    return d;
}

__global__ void prep_kernel(const float* __restrict__ W1, const float* __restrict__ b1,
                            const float* __restrict__ W2, const float* __restrict__ b2)
{
    const int i = blockIdx.x * blockDim.x + threadIdx.x;
    if (i < NJ * 56) {
        int j = i / 56, rem = i % 56, r = rem >> 3, c = rem & 7;
        float v = (c < 7) ? W1[j * 49 + r * 7 + c] : b1[j * 7 + r];
        gW1[i] = pack2(v, v);
    }
    if (i < NJ * 48) {
        int j = i / 48, rem = i % 48, r = rem >> 3, c = rem & 7;
        float v = (c < 7) ? W2[j * 42 + r * 7 + c] : b2[j * 6 + r];
        gW2[i] = pack2(v, v);
    }
}

__global__ __launch_bounds__(TPB, 4)
void se1d_kernel(const float* __restrict__ x,
                 float* __restrict__ out,
                 int B)
{
    // skeleton parents; topo order is identity (parent[i] < i for all i)
    constexpr int PAR[NJ] = {-1,0,0,0,1,2,3,4,5,6,7,8,9,9,9,12,13,14,16,17,18,19,20,21};

    extern __shared__ char smem[];
    float* stage = reinterpret_cast<float*>(smem);   // TILE*ROWF*4 = 32 KB (staging only)

    const int t    = threadIdx.x;
    const int tile = blockIdx.x * TILE;

    // ---- x prefetch: 1 float4 chunk (4 joints) ahead, per sample row ----
    const int r0 = tile + t;
    const int r1 = tile + TPB + t;
    const bool v0 = r0 < B, v1 = r1 < B;
    const float4* px0 = reinterpret_cast<const float4*>(x + (size_t)r0 * NJ);
    const float4* px1 = reinterpret_cast<const float4*>(x + (size_t)r1 * NJ);
    const float4 fz = make_float4(0.f, 0.f, 0.f, 0.f);
    float4 ca = v0 ? px0[0] : fz;
    float4 cb = v1 ? px1[0] : fz;
    float4 na = fz, nb = fz;

    float4* out4 = reinterpret_cast<float4*>(out);
    u64 feat[NJ][6];   // fully unrolled; liveness keeps <=3 joints live
    const int sw = t & 7;

    #pragma unroll
    for (int j = 0; j < NJ; j++) {
        // issue next x chunk at the start of each 4-joint phase
        if ((j & 3) == 0) {
            const int q = (j >> 2) + 1;
            if (q < 6) { na = v0 ? px0[q] : fz; nb = v1 ? px1[q] : fz; }
        }
        // select this joint's x component (compile-time after unroll)
        const int cc = j & 3;
        float xa = (cc == 0) ? ca.x : (cc == 1) ? ca.y : (cc == 2) ? ca.z : ca.w;
        float xb = (cc == 0) ? cb.x : (cc == 1) ? cb.y : (cc == 2) ? cb.z : cb.w;
        const u64 xp = pack2(xa, xb);

        const int p = PAR[j];
        const ulonglong2* w1j = reinterpret_cast<const ulonglong2*>(gW1 + j * 56);

        // h = relu([x_j, parent_feat] @ W1^T + b1): 4x LDG.128 (L1-hit broadcast) per row
        u64 h[7];
        #pragma unroll
        for (int r = 0; r < 7; r++) {
            ulonglong2 q0 = __ldg(w1j + r * 4 + 0);
            ulonglong2 q1 = __ldg(w1j + r * 4 + 1);
            ulonglong2 q2 = __ldg(w1j + r * 4 + 2);
            ulonglong2 q3 = __ldg(w1j + r * 4 + 3);
            u64 acc = q3.y;                      // bias
            acc = ffma2(xp, q0.x, acc);
            if (p >= 0) {
                acc = ffma2(feat[p][0], q0.y, acc);
                acc = ffma2(feat[p][1], q1.x, acc);
                acc = ffma2(feat[p][2], q1.y, acc);
                acc = ffma2(feat[p][3], q2.x, acc);
                acc = ffma2(feat[p][4], q2.y, acc);
                acc = ffma2(feat[p][5], q3.x, acc);
            }
            float ha, hb; unpack2(acc, ha, hb);
            h[r] = pack2(fmaxf(ha, 0.f), fmaxf(hb, 0.f));
        }

        // o = relu(h @ W2^T + b2)
        const ulonglong2* w2j = reinterpret_cast<const ulonglong2*>(gW2 + j * 48);
        float olo[6], ohi[6];
        #pragma unroll
        for (int r = 0; r < 6; r++) {
            ulonglong2 q0 = __ldg(w2j + r * 4 + 0);
            ulonglong2 q1 = __ldg(w2j + r * 4 + 1);
            ulonglong2 q2 = __ldg(w2j + r * 4 + 2);
            ulonglong2 q3 = __ldg(w2j + r * 4 + 3);
            u64 acc = q3.y;                      // bias
            acc = ffma2(h[0], q0.x, acc);
            acc = ffma2(h[1], q0.y, acc);
            acc = ffma2(h[2], q1.x, acc);
            acc = ffma2(h[3], q1.y, acc);
            acc = ffma2(h[4], q2.x, acc);
            acc = ffma2(h[5], q2.y, acc);
            acc = ffma2(h[6], q3.x, acc);
            float oa, ob; unpack2(acc, oa, ob);
            oa = fmaxf(oa, 0.f); ob = fmaxf(ob, 0.f);
            olo[r] = oa; ohi[r] = ob;
            feat[j][r] = pack2(oa, ob);
        }

        // stage the 6 outputs for both samples (XOR-swizzled 16B chunks)
        {
            const int cbs = (j & 3) * 6;         // phase-local channel base (0..18)
            #pragma unroll
            for (int k2 = 0; k2 < 3; k2++) {
                const int e     = cbs + 2 * k2;  // compile-time
                const int chunk = e >> 2;
                const int off   = e & 3;
                const int so    = ((chunk ^ sw) << 2) + off;
                *reinterpret_cast<float2*>(&stage[t * ROWF + so]) =
                    make_float2(olo[2 * k2], olo[2 * k2 + 1]);
                *reinterpret_cast<float2*>(&stage[(t + TPB) * ROWF + so]) =
                    make_float2(ohi[2 * k2], ohi[2 * k2 + 1]);
            }
        }

        // every 4 joints: flush 24 staged channels with coalesced STG.128
        if ((j & 3) == 3) {
            const int ph = j >> 2;
            __syncthreads();
            #pragma unroll
            for (int i = 0; i < 12; i++) {       // TILE*6 float4 / TPB threads
                const int kk = t + i * TPB;
                const int s  = kk / 6;
                const int c4 = kk % 6;
                float4 v = *reinterpret_cast<const float4*>(
                    &stage[s * ROWF + ((c4 ^ (s & 7)) << 2)]);
                const int gr = tile + s;
                if (gr < B)
                    out4[(size_t)gr * 36 + ph * 6 + c4] = v;
            }
            __syncthreads();
            if (j + 1 < NJ) { ca = na; cb = nb; }   // rotate x prefetch
        }
    }
}

extern "C" void kernel_launch(void* const* d_in, const int* in_sizes, int n_in,
                              void* d_out, int out_size)
{
    const float* x  = (const float*)d_in[0];
    const float* W1 = (const float*)d_in[1];
    const float* b1 = (const float*)d_in[2];
    const float* W2 = (const float*)d_in[3];
    const float* b2 = (const float*)d_in[4];
    float* out = (float*)d_out;

    const int B = in_sizes[0] / NJ;

    // 1) materialize duplicated {w,w} weight tables in global memory
    prep_kernel<<<(NJ * 56 + TPB - 1) / TPB, TPB>>>(W1, b1, W2, b2);

    // 2) main kernel (same stream -> ordered after prep)
    const int blocks = (B + TILE - 1) / TILE;
    const size_t shm = (size_t)TILE * ROWF * 4;     // staging only: 32768 B
    cudaFuncSetAttribute(se1d_kernel, cudaFuncAttributeMaxDynamicSharedMemorySize, (int)shm);
    se1d_kernel<<<blocks, TPB, shm>>>(x, out, B);
}